// round 1
// baseline (speedup 1.0000x reference)
#include <cuda_runtime.h>
#include <cstdint>

#define NN 50000
#define EE 800000
#define DD 128

// Scratch (allocation-free rule: __device__ globals)
__device__ float g_agg[(size_t)NN * 128];
__device__ float g_fsum[NN * 3];
__device__ float g_cnt[NN];

__device__ __forceinline__ float silu_f(float x) {
    return x / (1.0f + __expf(-x));
}

// ---------------------------------------------------------------------------
// Edge kernel: per tile of 64 edges, fused
//   h1 = silu([h[row],h[col],radial] @ We1 + be1)
//   m  = silu(h1 @ We2 + be2)
//   t  = silu(m @ Wc1 + bc1); coef = t @ Wc2
//   atomics: agg[row]+=m ; f_sum[row]+=clip(coord_diff*coef) ; cnt[row]+=1
// 256 threads; thread (warp=ty, lane=tx) owns an 8x4 register tile
// (rows = edges ty*8..+7, cols = tx*4..+3).
// ---------------------------------------------------------------------------
__global__ __launch_bounds__(256, 2) void edge_kernel(
    const float* __restrict__ h, const float* __restrict__ coord_diff,
    const int* __restrict__ row, const int* __restrict__ col,
    const float* __restrict__ We1, const float* __restrict__ be1,
    const float* __restrict__ We2, const float* __restrict__ be2,
    const float* __restrict__ Wc1, const float* __restrict__ bc1,
    const float* __restrict__ Wc2)
{
    extern __shared__ float sm[];
    float* sB   = sm;              // [32][128] = 4096
    float* sA   = sB + 4096;       // [64][33]  = 2112 (padded)
    float* sH   = sA + 2112;       // [64][132] = 8448
    float* sM   = sH + 8448;       // [64][132] = 8448
    float* sRad = sM + 8448;       // [64]
    float* sCoef= sRad + 64;       // [64]
    int*   sRow = (int*)(sCoef + 64); // [64]
    int*   sCol = sRow + 64;          // [64]

    const int t    = threadIdx.x;
    const int lane = t & 31;
    const int warp = t >> 5;
    const int col0 = lane * 4;
    const int row0 = warp * 8;
    const int e0   = blockIdx.x * 64;

    if (t < 64) {
        int e = e0 + t;
        sRow[t] = row[e];
        sCol[t] = col[e];
        float cx = coord_diff[e * 3 + 0];
        float cy = coord_diff[e * 3 + 1];
        float cz = coord_diff[e * 3 + 2];
        sRad[t] = cx * cx + cy * cy + cz * cz;
    }
    __syncthreads();

    float acc[8][4];

    // ---- GEMM1: [64,257] @ We1[257,128] ; radial (k=256) + bias folded into init
    {
        float w[4], b[4];
#pragma unroll
        for (int j = 0; j < 4; j++) w[j] = We1[256 * 128 + col0 + j];
#pragma unroll
        for (int j = 0; j < 4; j++) b[j] = be1[col0 + j];
#pragma unroll
        for (int i = 0; i < 8; i++) {
            float r = sRad[row0 + i];
#pragma unroll
            for (int j = 0; j < 4; j++) acc[i][j] = b[j] + r * w[j];
        }
    }

    for (int kc = 0; kc < 8; kc++) {
        __syncthreads();
        // stage weight chunk [32][128]
        const float4* Wsrc = (const float4*)(We1 + kc * 32 * 128);
        float4* Bdst = (float4*)sB;
        Bdst[t]       = Wsrc[t];
        Bdst[t + 256] = Wsrc[t + 256];
        Bdst[t + 512] = Wsrc[t + 512];
        Bdst[t + 768] = Wsrc[t + 768];
        // gather A chunk: 64 edges x 32 k, float4 gathers from h
#pragma unroll
        for (int it = 0; it < 2; it++) {
            int i = t + it * 256;           // 0..511
            int e  = i >> 3;
            int kq = i & 7;
            int k  = kc * 32 + kq * 4;
            const float* src = (k < 128)
                ? (h + (size_t)sRow[e] * 128 + k)
                : (h + (size_t)sCol[e] * 128 + (k - 128));
            float4 v = *(const float4*)src;
            float* dst = sA + e * 33 + kq * 4;
            dst[0] = v.x; dst[1] = v.y; dst[2] = v.z; dst[3] = v.w;
        }
        __syncthreads();
#pragma unroll
        for (int kk = 0; kk < 32; kk++) {
            float4 bv = *(const float4*)(sB + kk * 128 + col0);
#pragma unroll
            for (int i = 0; i < 8; i++) {
                float a = sA[(row0 + i) * 33 + kk];   // warp-broadcast
                acc[i][0] += a * bv.x;
                acc[i][1] += a * bv.y;
                acc[i][2] += a * bv.z;
                acc[i][3] += a * bv.w;
            }
        }
    }
    // silu -> sH
#pragma unroll
    for (int i = 0; i < 8; i++) {
        float4 v;
        v.x = silu_f(acc[i][0]); v.y = silu_f(acc[i][1]);
        v.z = silu_f(acc[i][2]); v.w = silu_f(acc[i][3]);
        *(float4*)(sH + (row0 + i) * 132 + col0) = v;
    }

    // ---- GEMM2: m = silu(sH @ We2 + be2)
#pragma unroll
    for (int i = 0; i < 8; i++)
#pragma unroll
        for (int j = 0; j < 4; j++) acc[i][j] = be2[col0 + j];

    for (int kc = 0; kc < 4; kc++) {
        __syncthreads();
        const float4* Wsrc = (const float4*)(We2 + kc * 32 * 128);
        float4* Bdst = (float4*)sB;
        Bdst[t]       = Wsrc[t];
        Bdst[t + 256] = Wsrc[t + 256];
        Bdst[t + 512] = Wsrc[t + 512];
        Bdst[t + 768] = Wsrc[t + 768];
        __syncthreads();
#pragma unroll
        for (int kk = 0; kk < 32; kk++) {
            float4 bv = *(const float4*)(sB + kk * 128 + col0);
            int kg = kc * 32 + kk;
#pragma unroll
            for (int i = 0; i < 8; i++) {
                float a = sH[(row0 + i) * 132 + kg];
                acc[i][0] += a * bv.x;
                acc[i][1] += a * bv.y;
                acc[i][2] += a * bv.z;
                acc[i][3] += a * bv.w;
            }
        }
    }
#pragma unroll
    for (int i = 0; i < 8; i++) {
        float4 v;
        v.x = silu_f(acc[i][0]); v.y = silu_f(acc[i][1]);
        v.z = silu_f(acc[i][2]); v.w = silu_f(acc[i][3]);
        *(float4*)(sM + (row0 + i) * 132 + col0) = v;
    }

    // ---- GEMM3: t = silu(sM @ Wc1 + bc1); coef = t @ Wc2
#pragma unroll
    for (int i = 0; i < 8; i++)
#pragma unroll
        for (int j = 0; j < 4; j++) acc[i][j] = bc1[col0 + j];

    for (int kc = 0; kc < 4; kc++) {
        __syncthreads();
        const float4* Wsrc = (const float4*)(Wc1 + kc * 32 * 128);
        float4* Bdst = (float4*)sB;
        Bdst[t]       = Wsrc[t];
        Bdst[t + 256] = Wsrc[t + 256];
        Bdst[t + 512] = Wsrc[t + 512];
        Bdst[t + 768] = Wsrc[t + 768];
        __syncthreads();
#pragma unroll
        for (int kk = 0; kk < 32; kk++) {
            float4 bv = *(const float4*)(sB + kk * 128 + col0);
            int kg = kc * 32 + kk;
#pragma unroll
            for (int i = 0; i < 8; i++) {
                float a = sM[(row0 + i) * 132 + kg];
                acc[i][0] += a * bv.x;
                acc[i][1] += a * bv.y;
                acc[i][2] += a * bv.z;
                acc[i][3] += a * bv.w;
            }
        }
    }
    {
        float wc[4];
#pragma unroll
        for (int j = 0; j < 4; j++) wc[j] = Wc2[col0 + j];
#pragma unroll
        for (int i = 0; i < 8; i++) {
            float v = silu_f(acc[i][0]) * wc[0] + silu_f(acc[i][1]) * wc[1]
                    + silu_f(acc[i][2]) * wc[2] + silu_f(acc[i][3]) * wc[3];
#pragma unroll
            for (int o = 16; o > 0; o >>= 1) v += __shfl_xor_sync(0xffffffffu, v, o);
            if (lane == 0) sCoef[row0 + i] = v;
        }
    }
    __syncthreads();

    // ---- scatter agg += m (coalesced over d within a warp)
    for (int i = t; i < 64 * 128; i += 256) {
        int e = i >> 7;
        int d = i & 127;
        atomicAdd(&g_agg[(size_t)sRow[e] * 128 + d], sM[e * 132 + d]);
    }
    // ---- force scatter
    if (t < 64) {
        int e = e0 + t;
        int r = sRow[t];
        float c = sCoef[t];
#pragma unroll
        for (int q = 0; q < 3; q++) {
            float v = coord_diff[e * 3 + q] * c;
            v = fminf(fmaxf(v, -100.0f), 100.0f);
            atomicAdd(&g_fsum[r * 3 + q], v);
        }
        atomicAdd(&g_cnt[r], 1.0f);
    }
}

// ---------------------------------------------------------------------------
// Node kernel: per tile of 64 nodes
//   h_out = silu([h,agg] @ Wn1 + bn1) @ Wn2 + bn2
//   vel   = silu(h @ Wv1 + bv1) @ Wv2 + bv2
//   force = f_sum / max(cnt, 1)
// out layout: [vel (N)] [force (N*3)] [h_out (N*128)]
// ---------------------------------------------------------------------------
__global__ __launch_bounds__(256, 3) void node_kernel(
    const float* __restrict__ h,
    const float* __restrict__ Wn1, const float* __restrict__ bn1,
    const float* __restrict__ Wn2, const float* __restrict__ bn2,
    const float* __restrict__ Wv1, const float* __restrict__ bv1,
    const float* __restrict__ Wv2, const float* __restrict__ bv2,
    float* __restrict__ out)
{
    extern __shared__ float sm[];
    float* sB   = sm;            // 4096
    float* sA   = sB + 4096;     // 2112
    float* sH   = sA + 2112;     // 8448
    float* sVel = sH + 8448;     // 64

    const int t    = threadIdx.x;
    const int lane = t & 31;
    const int warp = t >> 5;
    const int col0 = lane * 4;
    const int row0 = warp * 8;
    const int n0   = blockIdx.x * 64;

    float acc[8][4];

    // ---- GEMM1: [h,agg] @ Wn1 + bn1, K=256
#pragma unroll
    for (int i = 0; i < 8; i++)
#pragma unroll
        for (int j = 0; j < 4; j++) acc[i][j] = bn1[col0 + j];

    for (int kc = 0; kc < 8; kc++) {
        __syncthreads();
        const float4* Wsrc = (const float4*)(Wn1 + kc * 32 * 128);
        float4* Bdst = (float4*)sB;
        Bdst[t]       = Wsrc[t];
        Bdst[t + 256] = Wsrc[t + 256];
        Bdst[t + 512] = Wsrc[t + 512];
        Bdst[t + 768] = Wsrc[t + 768];
#pragma unroll
        for (int it = 0; it < 2; it++) {
            int i  = t + it * 256;
            int e  = i >> 3;
            int kq = i & 7;
            int n  = n0 + e;
            float4 v = make_float4(0.f, 0.f, 0.f, 0.f);
            if (n < NN) {
                int k = kc * 32 + kq * 4;
                const float* src = (k < 128)
                    ? (h + (size_t)n * 128 + k)
                    : (g_agg + (size_t)n * 128 + (k - 128));
                v = *(const float4*)src;
            }
            float* dst = sA + e * 33 + kq * 4;
            dst[0] = v.x; dst[1] = v.y; dst[2] = v.z; dst[3] = v.w;
        }
        __syncthreads();
#pragma unroll
        for (int kk = 0; kk < 32; kk++) {
            float4 bv = *(const float4*)(sB + kk * 128 + col0);
#pragma unroll
            for (int i = 0; i < 8; i++) {
                float a = sA[(row0 + i) * 33 + kk];
                acc[i][0] += a * bv.x;
                acc[i][1] += a * bv.y;
                acc[i][2] += a * bv.z;
                acc[i][3] += a * bv.w;
            }
        }
    }
#pragma unroll
    for (int i = 0; i < 8; i++) {
        float4 v;
        v.x = silu_f(acc[i][0]); v.y = silu_f(acc[i][1]);
        v.z = silu_f(acc[i][2]); v.w = silu_f(acc[i][3]);
        *(float4*)(sH + (row0 + i) * 132 + col0) = v;
    }

    // ---- GEMM2: h_out = sH @ Wn2 + bn2 (no activation)
#pragma unroll
    for (int i = 0; i < 8; i++)
#pragma unroll
        for (int j = 0; j < 4; j++) acc[i][j] = bn2[col0 + j];

    for (int kc = 0; kc < 4; kc++) {
        __syncthreads();
        const float4* Wsrc = (const float4*)(Wn2 + kc * 32 * 128);
        float4* Bdst = (float4*)sB;
        Bdst[t]       = Wsrc[t];
        Bdst[t + 256] = Wsrc[t + 256];
        Bdst[t + 512] = Wsrc[t + 512];
        Bdst[t + 768] = Wsrc[t + 768];
        __syncthreads();
#pragma unroll
        for (int kk = 0; kk < 32; kk++) {
            float4 bv = *(const float4*)(sB + kk * 128 + col0);
            int kg = kc * 32 + kk;
#pragma unroll
            for (int i = 0; i < 8; i++) {
                float a = sH[(row0 + i) * 132 + kg];
                acc[i][0] += a * bv.x;
                acc[i][1] += a * bv.y;
                acc[i][2] += a * bv.z;
                acc[i][3] += a * bv.w;
            }
        }
    }
    {
        float* outH = out + (size_t)4 * NN;
#pragma unroll
        for (int i = 0; i < 8; i++) {
            int n = n0 + row0 + i;
            if (n < NN) {
                float4 v;
                v.x = acc[i][0]; v.y = acc[i][1]; v.z = acc[i][2]; v.w = acc[i][3];
                *(float4*)(outH + (size_t)n * 128 + col0) = v;
            }
        }
    }

    // ---- vel head: v1 = silu(h @ Wv1 + bv1); vel = v1 @ Wv2 + bv2
#pragma unroll
    for (int i = 0; i < 8; i++)
#pragma unroll
        for (int j = 0; j < 4; j++) acc[i][j] = bv1[col0 + j];

    for (int kc = 0; kc < 4; kc++) {
        __syncthreads();
        const float4* Wsrc = (const float4*)(Wv1 + kc * 32 * 128);
        float4* Bdst = (float4*)sB;
        Bdst[t]       = Wsrc[t];
        Bdst[t + 256] = Wsrc[t + 256];
        Bdst[t + 512] = Wsrc[t + 512];
        Bdst[t + 768] = Wsrc[t + 768];
#pragma unroll
        for (int it = 0; it < 2; it++) {
            int i  = t + it * 256;
            int e  = i >> 3;
            int kq = i & 7;
            int n  = n0 + e;
            float4 v = make_float4(0.f, 0.f, 0.f, 0.f);
            if (n < NN) {
                int k = kc * 32 + kq * 4;
                v = *(const float4*)(h + (size_t)n * 128 + k);
            }
            float* dst = sA + e * 33 + kq * 4;
            dst[0] = v.x; dst[1] = v.y; dst[2] = v.z; dst[3] = v.w;
        }
        __syncthreads();
#pragma unroll
        for (int kk = 0; kk < 32; kk++) {
            float4 bv = *(const float4*)(sB + kk * 128 + col0);
#pragma unroll
            for (int i = 0; i < 8; i++) {
                float a = sA[(row0 + i) * 33 + kk];
                acc[i][0] += a * bv.x;
                acc[i][1] += a * bv.y;
                acc[i][2] += a * bv.z;
                acc[i][3] += a * bv.w;
            }
        }
    }
    {
        float wv[4];
#pragma unroll
        for (int j = 0; j < 4; j++) wv[j] = Wv2[col0 + j];
#pragma unroll
        for (int i = 0; i < 8; i++) {
            float v = silu_f(acc[i][0]) * wv[0] + silu_f(acc[i][1]) * wv[1]
                    + silu_f(acc[i][2]) * wv[2] + silu_f(acc[i][3]) * wv[3];
#pragma unroll
            for (int o = 16; o > 0; o >>= 1) v += __shfl_xor_sync(0xffffffffu, v, o);
            if (lane == 0) sVel[row0 + i] = v;
        }
    }
    __syncthreads();

    if (t < 64) {
        int n = n0 + t;
        if (n < NN) {
            out[n] = sVel[t] + bv2[0];
            float c = g_cnt[n];
            float inv = 1.0f / fmaxf(c, 1.0f);
            out[NN + (size_t)n * 3 + 0] = g_fsum[n * 3 + 0] * inv;
            out[NN + (size_t)n * 3 + 1] = g_fsum[n * 3 + 1] * inv;
            out[NN + (size_t)n * 3 + 2] = g_fsum[n * 3 + 2] * inv;
        }
    }
}

// ---------------------------------------------------------------------------
extern "C" void kernel_launch(void* const* d_in, const int* in_sizes, int n_in,
                              void* d_out, int out_size)
{
    const float* h          = (const float*)d_in[0];
    const float* coord_diff = (const float*)d_in[1];
    const int*   row        = (const int*)  d_in[2];
    const int*   col        = (const int*)  d_in[3];
    const float* We1 = (const float*)d_in[4];
    const float* be1 = (const float*)d_in[5];
    const float* We2 = (const float*)d_in[6];
    const float* be2 = (const float*)d_in[7];
    const float* Wn1 = (const float*)d_in[8];
    const float* bn1 = (const float*)d_in[9];
    const float* Wn2 = (const float*)d_in[10];
    const float* bn2 = (const float*)d_in[11];
    const float* Wc1 = (const float*)d_in[12];
    const float* bc1 = (const float*)d_in[13];
    const float* Wc2 = (const float*)d_in[14];
    const float* Wv1 = (const float*)d_in[15];
    const float* bv1 = (const float*)d_in[16];
    const float* Wv2 = (const float*)d_in[17];
    const float* bv2 = (const float*)d_in[18];
    float* out = (float*)d_out;

    void *aggp, *fsump, *cntp;
    cudaGetSymbolAddress(&aggp, g_agg);
    cudaGetSymbolAddress(&fsump, g_fsum);
    cudaGetSymbolAddress(&cntp, g_cnt);
    cudaMemsetAsync(aggp,  0, (size_t)NN * 128 * sizeof(float));
    cudaMemsetAsync(fsump, 0, (size_t)NN * 3 * sizeof(float));
    cudaMemsetAsync(cntp,  0, (size_t)NN * sizeof(float));

    const size_t smE = (size_t)(4096 + 2112 + 8448 + 8448 + 64 + 64 + 64 + 64) * sizeof(float);
    cudaFuncSetAttribute(edge_kernel, cudaFuncAttributeMaxDynamicSharedMemorySize, (int)smE);
    edge_kernel<<<EE / 64, 256, smE>>>(h, coord_diff, row, col,
                                       We1, be1, We2, be2, Wc1, bc1, Wc2);

    const size_t smN = (size_t)(4096 + 2112 + 8448 + 64) * sizeof(float);
    cudaFuncSetAttribute(node_kernel, cudaFuncAttributeMaxDynamicSharedMemorySize, (int)smN);
    node_kernel<<<(NN + 63) / 64, 256, smN>>>(h, Wn1, bn1, Wn2, bn2,
                                              Wv1, bv1, Wv2, bv2, out);
}